// round 7
// baseline (speedup 1.0000x reference)
#include <cuda_runtime.h>
#include <cuda_bf16.h>
#include <math_constants.h>
#include <stdint.h>

#define B_  2048
#define E_  128
#define V_  100000
#define VP_ 100032          // padded logits row stride (64-aligned)
#define NS_ 1563            // ceil(V/64) N-subtiles of 64
#define NG_ 27              // n groups; grid = 16 x 27 = 432 CTAs (one wave @ 3/SM)

#define LDSA 136                       // smem row stride in bf16 (128 + 8 pad)
#define SM_A    0                      // 128 x 272B = 34816
#define SM_B0   34816                  // 64 x 272B  = 17408
#define SM_B1   52224
#define SM_BIA0 69632                  // 64 floats
#define SM_BIA1 69888
#define SM_SUM  70144                  // 128 x 2 floats
#define SMEM_BYTES 71168

// ---- scratch (no allocation allowed; device globals) ----
__device__ __nv_bfloat16 g_embb[B_ * E_];             // emb+bias, bf16
__device__ __nv_bfloat16 g_woutb[(size_t)V_ * E_];    // W_out bf16 (25.6 MB)
__device__ __nv_bfloat16 g_logits[(size_t)B_ * VP_];  // bf16 logits, padded stride
__device__ float g_psum[(size_t)NS_ * B_];            // [subtile][row] sumexp partials
__device__ float g_lse[B_];
__device__ int   g_is64;

// ================= helpers =================
__device__ __forceinline__ uint32_t smem_u32(const void* p) {
    uint32_t a;
    asm("{ .reg .u64 t; cvta.to.shared.u64 t, %1; cvt.u32.u64 %0, t; }" : "=r"(a) : "l"(p));
    return a;
}
__device__ __forceinline__ void cp16(uint32_t dst, const void* src) {
    asm volatile("cp.async.cg.shared.global [%0], [%1], 16;" :: "r"(dst), "l"(src));
}
__device__ __forceinline__ void cp16z(uint32_t dst, const void* src, int bytes) {
    asm volatile("cp.async.cg.shared.global [%0], [%1], 16, %2;"
                 :: "r"(dst), "l"(src), "r"(bytes));
}
#define CP_COMMIT() asm volatile("cp.async.commit_group;" ::: "memory")
#define CP_WAIT1()  asm volatile("cp.async.wait_group 1;" ::: "memory")

__device__ __forceinline__ void ldsm4(uint32_t* d, uint32_t a) {
    asm volatile("ldmatrix.sync.aligned.m8n8.x4.shared.b16 {%0,%1,%2,%3}, [%4];"
        : "=r"(d[0]), "=r"(d[1]), "=r"(d[2]), "=r"(d[3]) : "r"(a));
}
__device__ __forceinline__ void mma16816(float* c, const uint32_t* a, const uint32_t* b) {
    asm volatile("mma.sync.aligned.m16n8k16.row.col.f32.bf16.bf16.f32 "
        "{%0,%1,%2,%3}, {%4,%5,%6,%7}, {%8,%9}, {%0,%1,%2,%3};"
        : "+f"(c[0]), "+f"(c[1]), "+f"(c[2]), "+f"(c[3])
        : "r"(a[0]), "r"(a[1]), "r"(a[2]), "r"(a[3]), "r"(b[0]), "r"(b[1]));
}

// ---- dtype detection for center_word (jax int64 may actually be int32) ----
__global__ void k_detect(const void* __restrict__ cw) {
    __shared__ int ok;
    if (threadIdx.x == 0) ok = 1;
    __syncthreads();
    const int2* p = (const int2*)cw;
    int bad = 0;
    for (int i = threadIdx.x; i < 1024; i += 256) {
        int2 v = p[i];
        if (v.y != 0 || v.x < 0 || v.x >= V_) bad = 1;
    }
    if (bad) atomicAnd(&ok, 0);
    __syncthreads();
    if (threadIdx.x == 0) g_is64 = ok;
}

__global__ void k_gather(const void* __restrict__ cw,
                         const float* __restrict__ Wc,
                         const float* __restrict__ bc) {
    int b = blockIdx.x, e = threadIdx.x;
    long long idx;
    if (g_is64) idx = ((const long long*)cw)[b];
    else        idx = (long long)(((const int*)cw)[b]);
    float v = Wc[(size_t)e * V_ + idx] + bc[e];
    g_embb[b * E_ + e] = __float2bfloat16(v);
}

__global__ void k_cvt(const float* __restrict__ W) {
    size_t i = (size_t)blockIdx.x * blockDim.x + threadIdx.x;
    const size_t n4 = (size_t)V_ * E_ / 4;
    if (i >= n4) return;
    float4 f = ((const float4*)W)[i];
    __nv_bfloat162* o = (__nv_bfloat162*)g_woutb;
    o[2 * i + 0] = __floats2bfloat162_rn(f.x, f.y);
    o[2 * i + 1] = __floats2bfloat162_rn(f.z, f.w);
}

// ================= GEMM: A-resident, B-streamed, one wave =================
// Grid (16, 27): blockIdx.x = mtile (A tile resident), blockIdx.y = g;
// CTA streams subtiles j = g + 27*t (64 N-rows each), cp.async double-buffered.
// 8 warps = 4(M) x 2(N); warp tile 32M x 32N; acc[2][4][4].
// Epilogue (no bounds checks; pad cols give exp(0)=1, removed in k_lse):
//   store bf16 logits (stride VP_) + coalesced per-(subtile,row) sumexp partials.
__global__ void __launch_bounds__(256, 3)
k_gemm(const float* __restrict__ b_out) {
    extern __shared__ __align__(1024) char smem[];
    const uint32_t sb = smem_u32(smem);
    float* sm_sum = (float*)(smem + SM_SUM);

    const int mtile = blockIdx.x, g = blockIdx.y;
    const int m0 = mtile * 128;
    const int cnt = (NS_ - g + NG_ - 1) / NG_;
    const int tid = threadIdx.x, lane = tid & 31, wid = tid >> 5;
    const int wm = wid >> 1, wn = wid & 1;

    // ---- stage loader: B subtile (64 rows x 128 bf16 = 64 x 256B) + bias ----
    auto load_stage = [&](int t) {
        const int j = g + t * NG_;
        const int n0 = j * 64;
        const uint32_t bdst = sb + (SM_B0 + (t & 1) * 17408);
        #pragma unroll
        for (int li = tid; li < 1024; li += 256) {     // 64 rows x 16 chunks of 16B
            int r = li >> 4, c = li & 15;
            int v = n0 + r;
            cp16z(bdst + (uint32_t)r * (LDSA * 2) + c * 16,
                  g_woutb + (size_t)(v < V_ ? v : 0) * E_ + c * 8, (v < V_) ? 16 : 0);
        }
        if (tid < 16) {
            int c4 = n0 + tid * 4;
            int valid = (c4 + 4 <= V_);
            cp16z(sb + (SM_BIA0 + (t & 1) * 256) + tid * 16,
                  b_out + (valid ? c4 : 0), valid ? 16 : 0);
        }
    };

    // ---- group 0: A tile + stage 0 ----
    #pragma unroll
    for (int li = tid; li < 2048; li += 256) {
        int r = li >> 4, c = li & 15;
        cp16(sb + SM_A + (uint32_t)r * (LDSA * 2) + c * 16,
             g_embb + (size_t)(m0 + r) * E_ + c * 8);
    }
    load_stage(0);
    CP_COMMIT();
    // ---- group 1: stage 1 ----
    if (cnt > 1) load_stage(1);
    CP_COMMIT();

    const uint32_t a_row0 = sb + SM_A + (uint32_t)(wm * 32 + (lane & 15)) * (LDSA * 2)
                          + ((lane >> 4) << 3) * 2;
    const uint32_t b_lane = (uint32_t)(wn * 32 + (lane & 7) + ((lane >> 4) << 3)) * (LDSA * 2)
                          + (((lane >> 3) & 1) << 3) * 2;

    for (int t = 0; t < cnt; t++) {
        const int j = g + t * NG_;
        const size_t n0 = (size_t)j * 64;
        const uint32_t bbase = sb + (SM_B0 + (t & 1) * 17408) + b_lane;
        const float* bia = (const float*)(smem + SM_BIA0 + (t & 1) * 256);

        CP_WAIT1();          // stage t complete (stage t+1 may pend)
        __syncthreads();

        // ---- mma 128x64x128 ----
        float acc[2][4][4];
        #pragma unroll
        for (int i = 0; i < 2; i++)
            #pragma unroll
            for (int jf = 0; jf < 4; jf++)
                #pragma unroll
                for (int k = 0; k < 4; k++) acc[i][jf][k] = 0.f;

        #pragma unroll
        for (int ks = 0; ks < 8; ks++) {
            const uint32_t koff = (uint32_t)(ks * 16) * 2;
            uint32_t a0[4], a1[4], b0[4], b1[4];
            ldsm4(a0, a_row0 + koff);
            ldsm4(a1, a_row0 + 16 * (LDSA * 2) + koff);
            ldsm4(b0, bbase + koff);
            ldsm4(b1, bbase + 16 * (LDSA * 2) + koff);
            mma16816(acc[0][0], a0, b0 + 0);
            mma16816(acc[0][1], a0, b0 + 2);
            mma16816(acc[0][2], a0, b1 + 0);
            mma16816(acc[0][3], a0, b1 + 2);
            mma16816(acc[1][0], a1, b0 + 0);
            mma16816(acc[1][1], a1, b0 + 2);
            mma16816(acc[1][2], a1, b1 + 0);
            mma16816(acc[1][3], a1, b1 + 2);
        }

        // ---- epilogue: bf16 logits + sumexp partials (unguarded; pad ok) ----
        #pragma unroll
        for (int mf = 0; mf < 2; mf++)
            #pragma unroll
            for (int h = 0; h < 2; h++) {
                const int rl = wm * 32 + mf * 16 + (lane >> 2) + h * 8;
                const size_t rowbase = (size_t)(m0 + rl) * VP_ + n0;
                float rs = 0.f;
                #pragma unroll
                for (int nf = 0; nf < 4; nf++) {
                    const int c = wn * 32 + nf * 8 + ((lane & 3) << 1);
                    float x0 = acc[mf][nf][h * 2 + 0] + bia[c];
                    float x1 = acc[mf][nf][h * 2 + 1] + bia[c + 1];
                    rs += __expf(x0) + __expf(x1);
                    __stcs((__nv_bfloat162*)(g_logits + rowbase + c),
                           __floats2bfloat162_rn(x0, x1));
                }
                rs += __shfl_xor_sync(0xffffffffu, rs, 1);
                rs += __shfl_xor_sync(0xffffffffu, rs, 2);
                if ((lane & 3) == 0) sm_sum[rl * 2 + wn] = rs;
            }
        __syncthreads();     // sm_sum ready AND all reads of buf(t&1) done
        if (tid < 128)
            g_psum[(size_t)j * B_ + m0 + tid] = sm_sum[tid * 2] + sm_sum[tid * 2 + 1];

        // ---- prefetch stage t+2 into buf(t&1); unconditional commit keeps
        //      group counting aligned with wait_group 1 at the tail ----
        if (t + 2 < cnt) load_stage(t + 2);
        CP_COMMIT();
    }
}

// ---- combine partials -> per-row LSE. Pad columns contribute exactly 32. ----
__global__ void k_lse() {
    __shared__ float sm[4][64];
    const int tid = threadIdx.x;
    const int r = (blockIdx.x << 6) + (tid & 63);
    const int jl = tid >> 6;
    float S = 0.f;
    for (int j = jl; j < NS_; j += 4)
        S += g_psum[(size_t)j * B_ + r];
    sm[jl][tid & 63] = S;
    __syncthreads();
    if (tid < 64) {
        float s = sm[0][tid] + sm[1][tid] + sm[2][tid] + sm[3][tid] - 32.0f;
        g_lse[(blockIdx.x << 6) + tid] = __logf(s);
    }
}

// ---- streaming fixup: out = bf16_logit - lse[row] ----
__global__ void __launch_bounds__(256) k_fix(float* __restrict__ out) {
    const int row = blockIdx.y;
    const int chunk = blockIdx.x * 256 + threadIdx.x;   // uint4 index in row
    if (chunk >= V_ / 8) return;
    const float l = g_lse[row];
    const uint4 v = __ldcs((const uint4*)(g_logits + (size_t)row * VP_) + chunk);
    const __nv_bfloat162* bp = (const __nv_bfloat162*)&v;
    float4 o0, o1;
    float2 f;
    f = __bfloat1622float2(bp[0]); o0.x = f.x - l; o0.y = f.y - l;
    f = __bfloat1622float2(bp[1]); o0.z = f.x - l; o0.w = f.y - l;
    f = __bfloat1622float2(bp[2]); o1.x = f.x - l; o1.y = f.y - l;
    f = __bfloat1622float2(bp[3]); o1.z = f.x - l; o1.w = f.y - l;
    float4* dst = (float4*)(out + (size_t)row * V_ + (size_t)chunk * 8);
    __stcs(dst + 0, o0);
    __stcs(dst + 1, o1);
}

extern "C" void kernel_launch(void* const* d_in, const int* in_sizes, int n_in,
                              void* d_out, int out_size) {
    const void*  cw = d_in[0];
    const float* Wc = (const float*)d_in[1];
    const float* bc = (const float*)d_in[2];
    const float* Wo = (const float*)d_in[3];
    const float* bo = (const float*)d_in[4];
    float* out = (float*)d_out;

    cudaFuncSetAttribute(k_gemm, cudaFuncAttributeMaxDynamicSharedMemorySize, SMEM_BYTES);

    k_detect<<<1, 256>>>(cw);
    k_gather<<<B_, 128>>>(cw, Wc, bc);
    k_cvt<<<((V_ * E_ / 4) + 255) / 256, 256>>>(Wo);
    k_gemm<<<dim3(16, NG_), 256, SMEM_BYTES>>>(bo);
    k_lse<<<32, 256>>>();
    k_fix<<<dim3((V_ / 8 + 255) / 256, B_), 256>>>(out);
}

// round 8
// speedup vs baseline: 1.0633x; 1.0633x over previous
#include <cuda_runtime.h>
#include <cuda_bf16.h>
#include <math_constants.h>
#include <stdint.h>

#define B_  2048
#define E_  128
#define V_  100000
#define NT_ 782   // ceil(V/128)
#define MT_ 16    // B/128

#define LOG2E_ 1.4426950408889634f
#define LN2_   0.6931471805599453f

#define LDSA 136                     // smem row stride in bf16 (128 + 8 pad)
#define TILE_BYTES (128 * LDSA * 2)  // 34816 per tile buffer
#define SM_A  0
#define SM_B  TILE_BYTES
#define SM_BO (2 * TILE_BYTES)             // 512 B bias (pre-scaled by log2e)
#define SM_SUM (2 * TILE_BYTES + 512)      // 1024 B row partials
#define SMEM_BYTES (2 * TILE_BYTES + 512 + 1024)   // 71168

// ---- scratch (no allocation allowed; device globals) ----
__device__ __nv_bfloat16 g_embb[B_ * E_];            // emb * log2e, bf16
__device__ __nv_bfloat16 g_woutb[(size_t)V_ * E_];   // W_out bf16 (25.6 MB)
__device__ __nv_bfloat16 g_logits[(size_t)B_ * V_];  // bf16 scaled logits (logit*log2e)
__device__ float g_psum[(size_t)B_ * NT_];           // per (row, ntile) sumexp
__device__ float g_lse[B_];
__device__ int   g_is64;

// ================= helpers =================
__device__ __forceinline__ uint32_t smem_u32(const void* p) {
    uint32_t a;
    asm("{ .reg .u64 t; cvta.to.shared.u64 t, %1; cvt.u32.u64 %0, t; }" : "=r"(a) : "l"(p));
    return a;
}
__device__ __forceinline__ float ex2(float x) {
    float y;
    asm("ex2.approx.ftz.f32 %0, %1;" : "=f"(y) : "f"(x));
    return y;
}
__device__ __forceinline__ void cp16(uint32_t dst, const void* src) {
    asm volatile("cp.async.cg.shared.global [%0], [%1], 16;" :: "r"(dst), "l"(src));
}
__device__ __forceinline__ void cp16z(uint32_t dst, const void* src, int bytes) {
    asm volatile("cp.async.cg.shared.global [%0], [%1], 16, %2;"
                 :: "r"(dst), "l"(src), "r"(bytes));
}
#define CP_COMMIT() asm volatile("cp.async.commit_group;" ::: "memory")
#define CP_WAIT0()  asm volatile("cp.async.wait_group 0;" ::: "memory")

__device__ __forceinline__ void ldsm4(uint32_t* d, uint32_t a) {
    asm volatile("ldmatrix.sync.aligned.m8n8.x4.shared.b16 {%0,%1,%2,%3}, [%4];"
        : "=r"(d[0]), "=r"(d[1]), "=r"(d[2]), "=r"(d[3]) : "r"(a));
}
__device__ __forceinline__ void mma16816(float* c, const uint32_t* a, const uint32_t* b) {
    asm volatile("mma.sync.aligned.m16n8k16.row.col.f32.bf16.bf16.f32 "
        "{%0,%1,%2,%3}, {%4,%5,%6,%7}, {%8,%9}, {%0,%1,%2,%3};"
        : "+f"(c[0]), "+f"(c[1]), "+f"(c[2]), "+f"(c[3])
        : "r"(a[0]), "r"(a[1]), "r"(a[2]), "r"(a[3]), "r"(b[0]), "r"(b[1]));
}

// ---- dtype detection for center_word (jax int64 may actually be int32) ----
__global__ void k_detect(const void* __restrict__ cw) {
    __shared__ int ok;
    if (threadIdx.x == 0) ok = 1;
    __syncthreads();
    const int2* p = (const int2*)cw;
    int bad = 0;
    for (int i = threadIdx.x; i < 1024; i += 256) {
        int2 v = p[i];
        if (v.y != 0 || v.x < 0 || v.x >= V_) bad = 1;
    }
    if (bad) atomicAnd(&ok, 0);
    __syncthreads();
    if (threadIdx.x == 0) g_is64 = ok;
}

// emb scaled by log2e so the epilogue exp becomes a bare ex2
__global__ void k_gather(const void* __restrict__ cw,
                         const float* __restrict__ Wc,
                         const float* __restrict__ bc) {
    int b = blockIdx.x, e = threadIdx.x;
    long long idx;
    if (g_is64) idx = ((const long long*)cw)[b];
    else        idx = (long long)(((const int*)cw)[b]);
    float v = (Wc[(size_t)e * V_ + idx] + bc[e]) * LOG2E_;
    g_embb[b * E_ + e] = __float2bfloat16(v);
}

__global__ void k_cvt(const float* __restrict__ W) {
    size_t i = (size_t)blockIdx.x * blockDim.x + threadIdx.x;
    const size_t n4 = (size_t)V_ * E_ / 4;
    if (i >= n4) return;
    float4 f = ((const float4*)W)[i];
    __nv_bfloat162* o = (__nv_bfloat162*)g_woutb;
    o[2 * i + 0] = __floats2bfloat162_rn(f.x, f.y);
    o[2 * i + 1] = __floats2bfloat162_rn(f.z, f.w);
}

// ================= single GEMM pass =================
// One CTA per N-tile (128 cols of V), persistent over 16 M-tiles.
// 8 warps: 4(M) x 2(N); each warp 32M x 64N as two 32-col halves
// (#pragma unroll 1) to keep live accumulators small -> 3 CTAs/SM.
// acc is logit*log2e; epilogue: ex2 for sumexp + bf16 store of scaled logit.
// A reload for the next M-tile is issued right after the last A read (hh==1
// mainloop) so the cp.async latency hides under the epilogue.
__global__ void __launch_bounds__(256, 3)
k_gemm(const float* __restrict__ b_out) {
    extern __shared__ __align__(1024) char smem[];
    const uint32_t sb = smem_u32(smem);
    float* bo_s   = (float*)(smem + SM_BO);
    float* sm_sum = (float*)(smem + SM_SUM);

    const int ntile = blockIdx.x;
    const int n0 = ntile * 128;
    const bool full = (n0 + 128 <= V_);
    const int tid = threadIdx.x, lane = tid & 31, wid = tid >> 5;
    const int wm = wid >> 1, wn = wid & 1;

    if (tid < 128) bo_s[tid] = (n0 + tid < V_) ? b_out[n0 + tid] * LOG2E_ : 0.f;

    // ---- B tile (once) + A tile 0 ----
    #pragma unroll
    for (int li = tid; li < 2048; li += 256) {
        int r = li >> 4, c = li & 15;
        int v = n0 + r;
        cp16z(sb + SM_B + (uint32_t)r * (LDSA * 2) + c * 16,
              g_woutb + (size_t)(v < V_ ? v : 0) * E_ + c * 8, (v < V_) ? 16 : 0);
    }
    #pragma unroll
    for (int li = tid; li < 2048; li += 256) {
        int r = li >> 4, c = li & 15;
        cp16(sb + SM_A + (uint32_t)r * (LDSA * 2) + c * 16,
             g_embb + (size_t)r * E_ + c * 8);
    }
    CP_COMMIT();
    CP_WAIT0();
    __syncthreads();

    const uint32_t a_row0 = sb + SM_A + (uint32_t)(wm * 32 + (lane & 15)) * (LDSA * 2)
                          + ((lane >> 4) << 3) * 2;
    const uint32_t b_rowb = sb + SM_B + (uint32_t)((lane & 7) + ((lane >> 4) << 3)) * (LDSA * 2)
                          + (((lane >> 3) & 1) << 3) * 2;

    for (int it = 0; it < MT_; it++) {
        const int m0 = it * 128;
        float rs[4];   // row partial sums per (mf,h)
        rs[0] = rs[1] = rs[2] = rs[3] = 0.f;

        #pragma unroll 1
        for (int hh = 0; hh < 2; hh++) {
            const int bcol = wn * 64 + hh * 32;
            float acc[2][4][4];
            #pragma unroll
            for (int i = 0; i < 2; i++)
                #pragma unroll
                for (int j = 0; j < 4; j++)
                    #pragma unroll
                    for (int k = 0; k < 4; k++) acc[i][j][k] = 0.f;

            #pragma unroll
            for (int ks = 0; ks < 8; ks++) {
                const uint32_t koff = (uint32_t)(ks * 16) * 2;
                uint32_t a0[4], a1[4], b0[4], b1[4];
                ldsm4(a0, a_row0 + koff);
                ldsm4(a1, a_row0 + 16 * (LDSA * 2) + koff);
                ldsm4(b0, b_rowb + (uint32_t)bcol * (LDSA * 2) + koff);
                ldsm4(b1, b_rowb + (uint32_t)(bcol + 16) * (LDSA * 2) + koff);
                mma16816(acc[0][0], a0, b0 + 0);
                mma16816(acc[0][1], a0, b0 + 2);
                mma16816(acc[0][2], a0, b1 + 0);
                mma16816(acc[0][3], a0, b1 + 2);
                mma16816(acc[1][0], a1, b0 + 0);
                mma16816(acc[1][1], a1, b0 + 2);
                mma16816(acc[1][2], a1, b1 + 0);
                mma16816(acc[1][3], a1, b1 + 2);
            }

            // After hh==1's mainloop all A reads for this tile are done:
            // kick the next A tile's cp.async so it overlaps the epilogue.
            if (hh == 1 && it + 1 < MT_) {
                __syncthreads();
                #pragma unroll
                for (int li = tid; li < 2048; li += 256) {
                    int r = li >> 4, c = li & 15;
                    cp16(sb + SM_A + (uint32_t)r * (LDSA * 2) + c * 16,
                         g_embb + (size_t)(m0 + 128 + r) * E_ + c * 8);
                }
                CP_COMMIT();
            }

            // epilogue: scaled logits (bf16, streaming) + 2^x partials
            #pragma unroll
            for (int mf = 0; mf < 2; mf++)
                #pragma unroll
                for (int h = 0; h < 2; h++) {
                    const int rg = m0 + wm * 32 + mf * 16 + (lane >> 2) + h * 8;
                    float t0 = 0.f, t1 = 0.f;
                    #pragma unroll
                    for (int nf = 0; nf < 4; nf++) {
                        const int c = bcol + nf * 8 + ((lane & 3) << 1);
                        if (full || n0 + c < V_) {   // V even; pair never straddles
                            float x0 = acc[mf][nf][h * 2 + 0] + bo_s[c];
                            float x1 = acc[mf][nf][h * 2 + 1] + bo_s[c + 1];
                            t0 += ex2(x0);
                            t1 += ex2(x1);
                            __stcs((__nv_bfloat162*)(g_logits + (size_t)rg * V_ + n0 + c),
                                   __floats2bfloat162_rn(x0, x1));
                        }
                    }
                    rs[mf * 2 + h] += t0 + t1;
                }
        }

        #pragma unroll
        for (int mf = 0; mf < 2; mf++)
            #pragma unroll
            for (int h = 0; h < 2; h++) {
                float t = rs[mf * 2 + h];
                t += __shfl_xor_sync(0xffffffffu, t, 1);
                t += __shfl_xor_sync(0xffffffffu, t, 2);
                if ((lane & 3) == 0) {
                    int rl = wm * 32 + mf * 16 + (lane >> 2) + h * 8;
                    sm_sum[rl * 2 + wn] = t;
                }
            }
        __syncthreads();
        if (tid < 128)
            g_psum[(size_t)(m0 + tid) * NT_ + ntile] =
                sm_sum[tid * 2] + sm_sum[tid * 2 + 1];

        if (it + 1 < MT_) {
            CP_WAIT0();      // next A tile (overlapped with epilogue above)
            __syncthreads();
        }
    }
}

// ---- combine chunk partials into per-row LSE ----
__global__ void k_lse() {
    int row = blockIdx.x, tid = threadIdx.x;
    __shared__ float sm[256];
    float S = 0.f;
    for (int c = tid; c < NT_; c += 256)
        S += g_psum[(size_t)row * NT_ + c];
    sm[tid] = S; __syncthreads();
    for (int s = 128; s > 0; s >>= 1) {
        if (tid < s) sm[tid] += sm[tid + s];
        __syncthreads();
    }
    if (tid == 0) g_lse[row] = __logf(sm[0]);
}

// ---- streaming fixup: out = scaled_logit * ln2 - lse[row] ----
__global__ void __launch_bounds__(256) k_fix(float* __restrict__ out) {
    const int row = blockIdx.y;
    const int chunk = blockIdx.x * 256 + threadIdx.x;   // uint4 index in row
    if (chunk >= V_ / 8) return;
    const float l = g_lse[row];
    const uint4 v = __ldcs((const uint4*)(g_logits + (size_t)row * V_) + chunk);
    const __nv_bfloat162* bp = (const __nv_bfloat162*)&v;
    float4 o0, o1;
    float2 f;
    f = __bfloat1622float2(bp[0]); o0.x = fmaf(f.x, LN2_, -l); o0.y = fmaf(f.y, LN2_, -l);
    f = __bfloat1622float2(bp[1]); o0.z = fmaf(f.x, LN2_, -l); o0.w = fmaf(f.y, LN2_, -l);
    f = __bfloat1622float2(bp[2]); o1.x = fmaf(f.x, LN2_, -l); o1.y = fmaf(f.y, LN2_, -l);
    f = __bfloat1622float2(bp[3]); o1.z = fmaf(f.x, LN2_, -l); o1.w = fmaf(f.y, LN2_, -l);
    float4* dst = (float4*)(out + (size_t)row * V_ + (size_t)chunk * 8);
    __stcs(dst + 0, o0);
    __stcs(dst + 1, o1);
}

extern "C" void kernel_launch(void* const* d_in, const int* in_sizes, int n_in,
                              void* d_out, int out_size) {
    const void*  cw = d_in[0];
    const float* Wc = (const float*)d_in[1];
    const float* bc = (const float*)d_in[2];
    const float* Wo = (const float*)d_in[3];
    const float* bo = (const float*)d_in[4];
    float* out = (float*)d_out;

    cudaFuncSetAttribute(k_gemm, cudaFuncAttributeMaxDynamicSharedMemorySize, SMEM_BYTES);

    k_detect<<<1, 256>>>(cw);
    k_gather<<<B_, 128>>>(cw, Wc, bc);
    k_cvt<<<((V_ * E_ / 4) + 255) / 256, 256>>>(Wo);
    k_gemm<<<NT_, 256, SMEM_BYTES>>>(bo);
    k_lse<<<B_, 256>>>();
    k_fix<<<dim3((V_ / 8 + 255) / 256, B_), 256>>>(out);
}

// round 9
// speedup vs baseline: 1.1160x; 1.0496x over previous
#include <cuda_runtime.h>
#include <cuda_bf16.h>
#include <math_constants.h>
#include <stdint.h>

#define B_  2048
#define E_  128
#define V_  100000
#define NT_ 782   // ceil(V/128)
#define MT_ 16    // B/128
#define PAD_ 96.0f   // NT_*128 - V_

#define LOG2E_ 1.4426950408889634f
#define LN2_   0.6931471805599453f

#define LDSA 136                     // smem row stride in bf16 (128 + 8 pad)
#define TILE_BYTES (128 * LDSA * 2)  // 34816 per tile buffer
#define SM_A  0
#define SM_B  TILE_BYTES
#define SM_BO (2 * TILE_BYTES)             // 512 B bias (pre-scaled by log2e)
#define SM_SUM (2 * TILE_BYTES + 512)      // 1024 B row partials
#define SM_STG (2 * TILE_BYTES + 512 + 1024)  // 8 warps x 640B staging
#define SMEM_BYTES (SM_STG + 8 * 640)         // 76288

// ---- scratch (no allocation allowed; device globals) ----
__device__ __nv_bfloat16 g_embb[B_ * E_];            // emb * log2e, bf16
__device__ __nv_bfloat16 g_woutb[(size_t)V_ * E_];   // W_out bf16 (25.6 MB)
__device__ __nv_bfloat16 g_logits[(size_t)B_ * V_];  // bf16 scaled logits (logit*log2e)
__device__ float g_psum[(size_t)NT_ * B_];           // [ntile][row] sumexp (coalesced)
__device__ float g_lse[B_];
__device__ int   g_is64;

// ================= helpers =================
__device__ __forceinline__ uint32_t smem_u32(const void* p) {
    uint32_t a;
    asm("{ .reg .u64 t; cvta.to.shared.u64 t, %1; cvt.u32.u64 %0, t; }" : "=r"(a) : "l"(p));
    return a;
}
__device__ __forceinline__ float ex2(float x) {
    float y;
    asm("ex2.approx.ftz.f32 %0, %1;" : "=f"(y) : "f"(x));
    return y;
}
__device__ __forceinline__ void cp16(uint32_t dst, const void* src) {
    asm volatile("cp.async.cg.shared.global [%0], [%1], 16;" :: "r"(dst), "l"(src));
}
__device__ __forceinline__ void cp16z(uint32_t dst, const void* src, int bytes) {
    asm volatile("cp.async.cg.shared.global [%0], [%1], 16, %2;"
                 :: "r"(dst), "l"(src), "r"(bytes));
}
#define CP_COMMIT() asm volatile("cp.async.commit_group;" ::: "memory")
#define CP_WAIT0()  asm volatile("cp.async.wait_group 0;" ::: "memory")

__device__ __forceinline__ void ldsm4(uint32_t* d, uint32_t a) {
    asm volatile("ldmatrix.sync.aligned.m8n8.x4.shared.b16 {%0,%1,%2,%3}, [%4];"
        : "=r"(d[0]), "=r"(d[1]), "=r"(d[2]), "=r"(d[3]) : "r"(a));
}
__device__ __forceinline__ void mma16816(float* c, const uint32_t* a, const uint32_t* b) {
    asm volatile("mma.sync.aligned.m16n8k16.row.col.f32.bf16.bf16.f32 "
        "{%0,%1,%2,%3}, {%4,%5,%6,%7}, {%8,%9}, {%0,%1,%2,%3};"
        : "+f"(c[0]), "+f"(c[1]), "+f"(c[2]), "+f"(c[3])
        : "r"(a[0]), "r"(a[1]), "r"(a[2]), "r"(a[3]), "r"(b[0]), "r"(b[1]));
}

// ---- dtype detection for center_word (jax int64 may actually be int32) ----
__global__ void k_detect(const void* __restrict__ cw) {
    __shared__ int ok;
    if (threadIdx.x == 0) ok = 1;
    __syncthreads();
    const int2* p = (const int2*)cw;
    int bad = 0;
    for (int i = threadIdx.x; i < 1024; i += 256) {
        int2 v = p[i];
        if (v.y != 0 || v.x < 0 || v.x >= V_) bad = 1;
    }
    if (bad) atomicAnd(&ok, 0);
    __syncthreads();
    if (threadIdx.x == 0) g_is64 = ok;
}

// emb scaled by log2e so the epilogue exp becomes a bare ex2
__global__ void k_gather(const void* __restrict__ cw,
                         const float* __restrict__ Wc,
                         const float* __restrict__ bc) {
    int b = blockIdx.x, e = threadIdx.x;
    long long idx;
    if (g_is64) idx = ((const long long*)cw)[b];
    else        idx = (long long)(((const int*)cw)[b]);
    float v = (Wc[(size_t)e * V_ + idx] + bc[e]) * LOG2E_;
    g_embb[b * E_ + e] = __float2bfloat16(v);
}

__global__ void k_cvt(const float* __restrict__ W) {
    size_t i = (size_t)blockIdx.x * blockDim.x + threadIdx.x;
    const size_t n4 = (size_t)V_ * E_ / 4;
    if (i >= n4) return;
    float4 f = ((const float4*)W)[i];
    __nv_bfloat162* o = (__nv_bfloat162*)g_woutb;
    o[2 * i + 0] = __floats2bfloat162_rn(f.x, f.y);
    o[2 * i + 1] = __floats2bfloat162_rn(f.z, f.w);
}

// ================= single GEMM pass =================
// One CTA per N-tile (128 cols of V), persistent over 16 M-tiles.
// 8 warps: 4(M) x 2(N); each warp 32M x 64N as two 32-col halves.
// Epilogue: per-(mf,h) group staged through per-warp smem (8 rows x 64B)
// -> one LDS.128 + one STG.128 per thread (coalesced) instead of 4 STG.32.
// No bounds checks in sums: pad cols (B rows zero-filled, bias 0) give
// ex2(0)=1; k_lse subtracts PAD_. Only STG keeps a 16B-chunk lane predicate.
__global__ void __launch_bounds__(256, 3)
k_gemm(const float* __restrict__ b_out) {
    extern __shared__ __align__(1024) char smem[];
    const uint32_t sb = smem_u32(smem);
    float* bo_s   = (float*)(smem + SM_BO);
    float* sm_sum = (float*)(smem + SM_SUM);

    const int ntile = blockIdx.x;
    const int n0 = ntile * 128;
    const int tid = threadIdx.x, lane = tid & 31, wid = tid >> 5;
    const int wm = wid >> 1, wn = wid & 1;

    if (tid < 128) bo_s[tid] = (n0 + tid < V_) ? b_out[n0 + tid] * LOG2E_ : 0.f;

    // ---- B tile (once) + A tile 0 ----
    #pragma unroll
    for (int li = tid; li < 2048; li += 256) {
        int r = li >> 4, c = li & 15;
        int v = n0 + r;
        cp16z(sb + SM_B + (uint32_t)r * (LDSA * 2) + c * 16,
              g_woutb + (size_t)(v < V_ ? v : 0) * E_ + c * 8, (v < V_) ? 16 : 0);
    }
    #pragma unroll
    for (int li = tid; li < 2048; li += 256) {
        int r = li >> 4, c = li & 15;
        cp16(sb + SM_A + (uint32_t)r * (LDSA * 2) + c * 16,
             g_embb + (size_t)r * E_ + c * 8);
    }
    CP_COMMIT();
    CP_WAIT0();
    __syncthreads();

    const uint32_t a_row0 = sb + SM_A + (uint32_t)(wm * 32 + (lane & 15)) * (LDSA * 2)
                          + ((lane >> 4) << 3) * 2;
    const uint32_t b_rowb = sb + SM_B + (uint32_t)((lane & 7) + ((lane >> 4) << 3)) * (LDSA * 2)
                          + (((lane >> 3) & 1) << 3) * 2;
    // per-warp staging: 8 rows x 80B
    char* stg = smem + SM_STG + wid * 640;
    const int qrow = lane >> 2, q = lane & 3;

    for (int it = 0; it < MT_; it++) {
        const int m0 = it * 128;
        float rs[4];
        rs[0] = rs[1] = rs[2] = rs[3] = 0.f;

        #pragma unroll 1
        for (int hh = 0; hh < 2; hh++) {
            const int bcol = wn * 64 + hh * 32;
            float acc[2][4][4];
            #pragma unroll
            for (int i = 0; i < 2; i++)
                #pragma unroll
                for (int j = 0; j < 4; j++)
                    #pragma unroll
                    for (int k = 0; k < 4; k++) acc[i][j][k] = 0.f;

            #pragma unroll
            for (int ks = 0; ks < 8; ks++) {
                const uint32_t koff = (uint32_t)(ks * 16) * 2;
                uint32_t a0[4], a1[4], b0[4], b1[4];
                ldsm4(a0, a_row0 + koff);
                ldsm4(a1, a_row0 + 16 * (LDSA * 2) + koff);
                ldsm4(b0, b_rowb + (uint32_t)bcol * (LDSA * 2) + koff);
                ldsm4(b1, b_rowb + (uint32_t)(bcol + 16) * (LDSA * 2) + koff);
                mma16816(acc[0][0], a0, b0 + 0);
                mma16816(acc[0][1], a0, b0 + 2);
                mma16816(acc[0][2], a0, b1 + 0);
                mma16816(acc[0][3], a0, b1 + 2);
                mma16816(acc[1][0], a1, b0 + 0);
                mma16816(acc[1][1], a1, b0 + 2);
                mma16816(acc[1][2], a1, b1 + 0);
                mma16816(acc[1][3], a1, b1 + 2);
            }

            // After hh==1's mainloop all A reads are done: kick next A tile.
            if (hh == 1 && it + 1 < MT_) {
                __syncthreads();
                #pragma unroll
                for (int li = tid; li < 2048; li += 256) {
                    int r = li >> 4, c = li & 15;
                    cp16(sb + SM_A + (uint32_t)r * (LDSA * 2) + c * 16,
                         g_embb + (size_t)(m0 + 128 + r) * E_ + c * 8);
                }
                CP_COMMIT();
            }

            // ---- epilogue: ex2 sums + staged coalesced bf16 logit store ----
            const int c0 = n0 + bcol;   // global col base for this warp-half
            #pragma unroll
            for (int mf = 0; mf < 2; mf++)
                #pragma unroll
                for (int h = 0; h < 2; h++) {
                    float t0 = 0.f, t1 = 0.f;
                    #pragma unroll
                    for (int nf = 0; nf < 4; nf++) {
                        const int c = bcol + nf * 8 + (q << 1);
                        float x0 = acc[mf][nf][h * 2 + 0] + bo_s[c];
                        float x1 = acc[mf][nf][h * 2 + 1] + bo_s[c + 1];
                        t0 += ex2(x0);
                        t1 += ex2(x1);
                        __nv_bfloat162 pk = __floats2bfloat162_rn(x0, x1);
                        *(uint32_t*)(stg + qrow * 80 + nf * 16 + q * 4) =
                            *(uint32_t*)&pk;
                    }
                    rs[mf * 2 + h] += t0 + t1;
                    __syncwarp();
                    // readback (LDS.128) + coalesced STG.128 (16B per lane)
                    {
                        float4 v = *(float4*)(stg + qrow * 80 + q * 16);
                        if (c0 + q * 8 < V_) {
                            const int rg = m0 + wm * 32 + mf * 16 + h * 8 + qrow;
                            __stcs((float4*)(g_logits + (size_t)rg * V_ + c0 + q * 8), v);
                        }
                    }
                    __syncwarp();
                }
        }

        #pragma unroll
        for (int mf = 0; mf < 2; mf++)
            #pragma unroll
            for (int h = 0; h < 2; h++) {
                float t = rs[mf * 2 + h];
                t += __shfl_xor_sync(0xffffffffu, t, 1);
                t += __shfl_xor_sync(0xffffffffu, t, 2);
                if ((lane & 3) == 0) {
                    int rl = wm * 32 + mf * 16 + (lane >> 2) + h * 8;
                    sm_sum[rl * 2 + wn] = t;
                }
            }
        __syncthreads();
        if (tid < 128)
            g_psum[(size_t)ntile * B_ + m0 + tid] =
                sm_sum[tid * 2] + sm_sum[tid * 2 + 1];

        if (it + 1 < MT_) {
            CP_WAIT0();      // next A tile (overlapped with epilogue above)
            __syncthreads();
        }
    }
}

// ---- combine partials -> per-row LSE; pad cols contribute exactly PAD_ ----
__global__ void k_lse() {   // grid 32, block 256
    __shared__ float sm[4][64];
    const int tid = threadIdx.x;
    const int r = (blockIdx.x << 6) + (tid & 63);
    const int jl = tid >> 6;
    float S = 0.f;
    for (int j = jl; j < NT_; j += 4)
        S += g_psum[(size_t)j * B_ + r];
    sm[jl][tid & 63] = S;
    __syncthreads();
    if (tid < 64) {
        float s = sm[0][tid] + sm[1][tid] + sm[2][tid] + sm[3][tid] - PAD_;
        g_lse[(blockIdx.x << 6) + tid] = __logf(s);
    }
}

// ---- streaming fixup: out = scaled_logit * ln2 - lse[row] ----
__global__ void __launch_bounds__(256) k_fix(float* __restrict__ out) {
    const int row = blockIdx.y;
    const int chunk = blockIdx.x * 256 + threadIdx.x;   // uint4 index in row
    if (chunk >= V_ / 8) return;
    const float l = g_lse[row];
    const uint4 v = __ldcs((const uint4*)(g_logits + (size_t)row * V_) + chunk);
    const __nv_bfloat162* bp = (const __nv_bfloat162*)&v;
    float4 o0, o1;
    float2 f;
    f = __bfloat1622float2(bp[0]); o0.x = fmaf(f.x, LN2_, -l); o0.y = fmaf(f.y, LN2_, -l);
    f = __bfloat1622float2(bp[1]); o0.z = fmaf(f.x, LN2_, -l); o0.w = fmaf(f.y, LN2_, -l);
    f = __bfloat1622float2(bp[2]); o1.x = fmaf(f.x, LN2_, -l); o1.y = fmaf(f.y, LN2_, -l);
    f = __bfloat1622float2(bp[3]); o1.z = fmaf(f.x, LN2_, -l); o1.w = fmaf(f.y, LN2_, -l);
    float4* dst = (float4*)(out + (size_t)row * V_ + (size_t)chunk * 8);
    __stcs(dst + 0, o0);
    __stcs(dst + 1, o1);
}

extern "C" void kernel_launch(void* const* d_in, const int* in_sizes, int n_in,
                              void* d_out, int out_size) {
    const void*  cw = d_in[0];
    const float* Wc = (const float*)d_in[1];
    const float* bc = (const float*)d_in[2];
    const float* Wo = (const float*)d_in[3];
    const float* bo = (const float*)d_in[4];
    float* out = (float*)d_out;

    cudaFuncSetAttribute(k_gemm, cudaFuncAttributeMaxDynamicSharedMemorySize, SMEM_BYTES);

    k_detect<<<1, 256>>>(cw);
    k_gather<<<B_, 128>>>(cw, Wc, bc);
    k_cvt<<<((V_ * E_ / 4) + 255) / 256, 256>>>(Wo);
    k_gemm<<<NT_, 256, SMEM_BYTES>>>(bo);
    k_lse<<<32, 256>>>();
    k_fix<<<dim3((V_ / 8 + 255) / 256, B_), 256>>>(out);
}

// round 10
// speedup vs baseline: 1.1661x; 1.0449x over previous
#include <cuda_runtime.h>
#include <cuda_bf16.h>
#include <math_constants.h>
#include <stdint.h>

#define B_  2048
#define E_  128
#define V_  100000
#define NT_ 782   // ceil(V/128)
#define MT_ 16    // B/128
#define PAD_ 96.0f   // NT_*128 - V_

#define LOG2E_ 1.4426950408889634f
#define LN2_   0.6931471805599453f

#define LDSA 136                     // smem row stride in bf16 (128 + 8 pad)
#define TILE_BYTES (128 * LDSA * 2)  // 34816 per tile buffer
#define SM_A0 0
#define SM_A1 TILE_BYTES
#define SM_B  (2 * TILE_BYTES)
#define SM_BO (3 * TILE_BYTES)             // 512 B bias (pre-scaled by log2e)
#define SM_SUM (3 * TILE_BYTES + 512)      // 1024 B row partials
#define SM_STG (3 * TILE_BYTES + 512 + 1024)  // 8 warps x 640B staging
#define SMEM_BYTES (SM_STG + 8 * 640)         // 111104

// ---- scratch (no allocation allowed; device globals) ----
__device__ __nv_bfloat16 g_embb[B_ * E_];            // emb * log2e, bf16
__device__ __nv_bfloat16 g_woutb[(size_t)V_ * E_];   // W_out bf16 (25.6 MB)
__device__ __nv_bfloat16 g_logits[(size_t)B_ * V_];  // bf16 scaled logits (logit*log2e)
__device__ float g_psum[(size_t)NT_ * B_];           // [ntile][row] sumexp (coalesced)
__device__ float g_lse[B_];
__device__ int   g_is64;

// ================= helpers =================
__device__ __forceinline__ uint32_t smem_u32(const void* p) {
    uint32_t a;
    asm("{ .reg .u64 t; cvta.to.shared.u64 t, %1; cvt.u32.u64 %0, t; }" : "=r"(a) : "l"(p));
    return a;
}
__device__ __forceinline__ float ex2(float x) {
    float y;
    asm("ex2.approx.ftz.f32 %0, %1;" : "=f"(y) : "f"(x));
    return y;
}
__device__ __forceinline__ void cp16(uint32_t dst, const void* src) {
    asm volatile("cp.async.cg.shared.global [%0], [%1], 16;" :: "r"(dst), "l"(src));
}
__device__ __forceinline__ void cp16z(uint32_t dst, const void* src, int bytes) {
    asm volatile("cp.async.cg.shared.global [%0], [%1], 16, %2;"
                 :: "r"(dst), "l"(src), "r"(bytes));
}
#define CP_COMMIT() asm volatile("cp.async.commit_group;" ::: "memory")
#define CP_WAIT0()  asm volatile("cp.async.wait_group 0;" ::: "memory")

__device__ __forceinline__ void ldsm4(uint32_t* d, uint32_t a) {
    asm volatile("ldmatrix.sync.aligned.m8n8.x4.shared.b16 {%0,%1,%2,%3}, [%4];"
        : "=r"(d[0]), "=r"(d[1]), "=r"(d[2]), "=r"(d[3]) : "r"(a));
}
__device__ __forceinline__ void mma16816(float* c, const uint32_t* a, const uint32_t* b) {
    asm volatile("mma.sync.aligned.m16n8k16.row.col.f32.bf16.bf16.f32 "
        "{%0,%1,%2,%3}, {%4,%5,%6,%7}, {%8,%9}, {%0,%1,%2,%3};"
        : "+f"(c[0]), "+f"(c[1]), "+f"(c[2]), "+f"(c[3])
        : "r"(a[0]), "r"(a[1]), "r"(a[2]), "r"(a[3]), "r"(b[0]), "r"(b[1]));
}

// ---- dtype detection for center_word (jax int64 may actually be int32) ----
__global__ void k_detect(const void* __restrict__ cw) {
    __shared__ int ok;
    if (threadIdx.x == 0) ok = 1;
    __syncthreads();
    const int2* p = (const int2*)cw;
    int bad = 0;
    for (int i = threadIdx.x; i < 1024; i += 256) {
        int2 v = p[i];
        if (v.y != 0 || v.x < 0 || v.x >= V_) bad = 1;
    }
    if (bad) atomicAnd(&ok, 0);
    __syncthreads();
    if (threadIdx.x == 0) g_is64 = ok;
}

// emb scaled by log2e so the epilogue exp becomes a bare ex2
__global__ void k_gather(const void* __restrict__ cw,
                         const float* __restrict__ Wc,
                         const float* __restrict__ bc) {
    int b = blockIdx.x, e = threadIdx.x;
    long long idx;
    if (g_is64) idx = ((const long long*)cw)[b];
    else        idx = (long long)(((const int*)cw)[b]);
    float v = (Wc[(size_t)e * V_ + idx] + bc[e]) * LOG2E_;
    g_embb[b * E_ + e] = __float2bfloat16(v);
}

__global__ void k_cvt(const float* __restrict__ W) {
    size_t i = (size_t)blockIdx.x * blockDim.x + threadIdx.x;
    const size_t n4 = (size_t)V_ * E_ / 4;
    if (i >= n4) return;
    float4 f = ((const float4*)W)[i];
    __nv_bfloat162* o = (__nv_bfloat162*)g_woutb;
    o[2 * i + 0] = __floats2bfloat162_rn(f.x, f.y);
    o[2 * i + 1] = __floats2bfloat162_rn(f.z, f.w);
}

// ================= single GEMM pass =================
// One CTA per N-tile (128 cols of V), persistent over 16 M-tiles.
// 8 warps: 4(M) x 2(N); FULL warp tile 32M x 64N (acc[2][8][4], 64 regs),
// 2 CTAs/SM (<=128 regs). A double-buffered: next tile's cp.async issued
// BEFORE the mainloop, waited after the epilogue -> fully hidden.
// Epilogue: per-(mf,h,sub) 32-col groups staged through per-warp smem ->
// one LDS.128 + one STG.128 per thread. No bounds checks in sums (pad cols
// give ex2(0)=1, k_lse subtracts PAD_); STG keeps a 16B-chunk predicate.
__global__ void __launch_bounds__(256, 2)
k_gemm(const float* __restrict__ b_out) {
    extern __shared__ __align__(1024) char smem[];
    const uint32_t sb = smem_u32(smem);
    float* bo_s   = (float*)(smem + SM_BO);
    float* sm_sum = (float*)(smem + SM_SUM);

    const int ntile = blockIdx.x;
    const int n0 = ntile * 128;
    const int tid = threadIdx.x, lane = tid & 31, wid = tid >> 5;
    const int wm = wid >> 1, wn = wid & 1;

    if (tid < 128) bo_s[tid] = (n0 + tid < V_) ? b_out[n0 + tid] * LOG2E_ : 0.f;

    // ---- B tile (once) + A tile 0 ----
    #pragma unroll
    for (int li = tid; li < 2048; li += 256) {
        int r = li >> 4, c = li & 15;
        int v = n0 + r;
        cp16z(sb + SM_B + (uint32_t)r * (LDSA * 2) + c * 16,
              g_woutb + (size_t)(v < V_ ? v : 0) * E_ + c * 8, (v < V_) ? 16 : 0);
    }
    #pragma unroll
    for (int li = tid; li < 2048; li += 256) {
        int r = li >> 4, c = li & 15;
        cp16(sb + SM_A0 + (uint32_t)r * (LDSA * 2) + c * 16,
             g_embb + (size_t)r * E_ + c * 8);
    }
    CP_COMMIT();
    CP_WAIT0();
    __syncthreads();

    const uint32_t a_lane = (uint32_t)(wm * 32 + (lane & 15)) * (LDSA * 2)
                          + ((lane >> 4) << 3) * 2;
    const uint32_t b_rowb = sb + SM_B
                          + (uint32_t)(wn * 64 + (lane & 7) + ((lane >> 4) << 3)) * (LDSA * 2)
                          + (((lane >> 3) & 1) << 3) * 2;
    char* stg = smem + SM_STG + wid * 640;   // per-warp staging: 8 rows x 80B
    const int qrow = lane >> 2, q = lane & 3;

    for (int it = 0; it < MT_; it++) {
        const int m0 = it * 128;
        const uint32_t a_base = sb + ((it & 1) ? SM_A1 : SM_A0) + a_lane;

        // prefetch next A tile into the other buffer (hidden under mainloop)
        if (it + 1 < MT_) {
            const uint32_t nb = sb + ((it & 1) ? SM_A0 : SM_A1);
            #pragma unroll
            for (int li = tid; li < 2048; li += 256) {
                int r = li >> 4, c = li & 15;
                cp16(nb + (uint32_t)r * (LDSA * 2) + c * 16,
                     g_embb + (size_t)(m0 + 128 + r) * E_ + c * 8);
            }
        }
        CP_COMMIT();

        // ---- mainloop: 128x128x128, full 32Mx64N warp tile ----
        float acc[2][8][4];
        #pragma unroll
        for (int i = 0; i < 2; i++)
            #pragma unroll
            for (int j = 0; j < 8; j++)
                #pragma unroll
                for (int k = 0; k < 4; k++) acc[i][j][k] = 0.f;

        #pragma unroll
        for (int ks = 0; ks < 8; ks++) {
            const uint32_t koff = (uint32_t)(ks * 16) * 2;
            uint32_t a0[4], a1[4], bb[4][4];
            ldsm4(a0, a_base + koff);
            ldsm4(a1, a_base + 16 * (LDSA * 2) + koff);
            #pragma unroll
            for (int nfp = 0; nfp < 4; nfp++)
                ldsm4(bb[nfp], b_rowb + (uint32_t)(nfp * 16) * (LDSA * 2) + koff);
            #pragma unroll
            for (int nfp = 0; nfp < 4; nfp++) {
                mma16816(acc[0][nfp * 2 + 0], a0, bb[nfp] + 0);
                mma16816(acc[0][nfp * 2 + 1], a0, bb[nfp] + 2);
                mma16816(acc[1][nfp * 2 + 0], a1, bb[nfp] + 0);
                mma16816(acc[1][nfp * 2 + 1], a1, bb[nfp] + 2);
            }
        }

        // ---- epilogue: ex2 sums + staged coalesced bf16 logit stores ----
        float rs[4];
        rs[0] = rs[1] = rs[2] = rs[3] = 0.f;
        #pragma unroll
        for (int mf = 0; mf < 2; mf++)
            #pragma unroll
            for (int h = 0; h < 2; h++) {
                #pragma unroll
                for (int sub = 0; sub < 2; sub++) {
                    float t0 = 0.f, t1 = 0.f;
                    #pragma unroll
                    for (int jn = 0; jn < 4; jn++) {
                        const int j = sub * 4 + jn;
                        const int c = wn * 64 + j * 8 + (q << 1);
                        float x0 = acc[mf][j][h * 2 + 0] + bo_s[c];
                        float x1 = acc[mf][j][h * 2 + 1] + bo_s[c + 1];
                        t0 += ex2(x0);
                        t1 += ex2(x1);
                        __nv_bfloat162 pk = __floats2bfloat162_rn(x0, x1);
                        *(uint32_t*)(stg + qrow * 80 + jn * 16 + q * 4) =
                            *(uint32_t*)&pk;
                    }
                    rs[mf * 2 + h] += t0 + t1;
                    __syncwarp();
                    {
                        float4 v = *(float4*)(stg + qrow * 80 + q * 16);
                        const int c0 = n0 + wn * 64 + sub * 32;
                        if (c0 + q * 8 < V_) {
                            const int rg = m0 + wm * 32 + mf * 16 + h * 8 + qrow;
                            __stcs((float4*)(g_logits + (size_t)rg * V_ + c0 + q * 8), v);
                        }
                    }
                    __syncwarp();
                }
            }

        #pragma unroll
        for (int mf = 0; mf < 2; mf++)
            #pragma unroll
            for (int h = 0; h < 2; h++) {
                float t = rs[mf * 2 + h];
                t += __shfl_xor_sync(0xffffffffu, t, 1);
                t += __shfl_xor_sync(0xffffffffu, t, 2);
                if (q == 0) sm_sum[(wm * 32 + mf * 16 + h * 8 + qrow) * 2 + wn] = t;
            }
        __syncthreads();
        if (tid < 128)
            g_psum[(size_t)ntile * B_ + m0 + tid] =
                sm_sum[tid * 2] + sm_sum[tid * 2 + 1];

        if (it + 1 < MT_) {
            CP_WAIT0();      // next A tile (overlapped with mainloop+epilogue)
            __syncthreads();
        }
    }
}

// ---- combine partials -> per-row LSE; pad cols contribute exactly PAD_ ----
__global__ void k_lse() {   // grid 32, block 256
    __shared__ float sm[4][64];
    const int tid = threadIdx.x;
    const int r = (blockIdx.x << 6) + (tid & 63);
    const int jl = tid >> 6;
    float S = 0.f;
    for (int j = jl; j < NT_; j += 4)
        S += g_psum[(size_t)j * B_ + r];
    sm[jl][tid & 63] = S;
    __syncthreads();
    if (tid < 64) {
        float s = sm[0][tid] + sm[1][tid] + sm[2][tid] + sm[3][tid] - PAD_;
        g_lse[(blockIdx.x << 6) + tid] = __logf(s);
    }
}

// ---- streaming fixup: out = scaled_logit * ln2 - lse[row] ----
__global__ void __launch_bounds__(256) k_fix(float* __restrict__ out) {
    const int row = blockIdx.y;
    const int chunk = blockIdx.x * 256 + threadIdx.x;   // uint4 index in row
    if (chunk >= V_ / 8) return;
    const float l = g_lse[row];
    const uint4 v = __ldcs((const uint4*)(g_logits + (size_t)row * V_) + chunk);
    const __nv_bfloat162* bp = (const __nv_bfloat162*)&v;
    float4 o0, o1;
    float2 f;
    f = __bfloat1622float2(bp[0]); o0.x = fmaf(f.x, LN2_, -l); o0.y = fmaf(f.y, LN2_, -l);
    f = __bfloat1622float2(bp[1]); o0.z = fmaf(f.x, LN2_, -l); o0.w = fmaf(f.y, LN2_, -l);
    f = __bfloat1622float2(bp[2]); o1.x = fmaf(f.x, LN2_, -l); o1.y = fmaf(f.y, LN2_, -l);
    f = __bfloat1622float2(bp[3]); o1.z = fmaf(f.x, LN2_, -l); o1.w = fmaf(f.y, LN2_, -l);
    float4* dst = (float4*)(out + (size_t)row * V_ + (size_t)chunk * 8);
    __stcs(dst + 0, o0);
    __stcs(dst + 1, o1);
}

extern "C" void kernel_launch(void* const* d_in, const int* in_sizes, int n_in,
                              void* d_out, int out_size) {
    const void*  cw = d_in[0];
    const float* Wc = (const float*)d_in[1];
    const float* bc = (const float*)d_in[2];
    const float* Wo = (const float*)d_in[3];
    const float* bo = (const float*)d_in[4];
    float* out = (float*)d_out;

    cudaFuncSetAttribute(k_gemm, cudaFuncAttributeMaxDynamicSharedMemorySize, SMEM_BYTES);

    k_detect<<<1, 256>>>(cw);
    k_gather<<<B_, 128>>>(cw, Wc, bc);
    k_cvt<<<((V_ * E_ / 4) + 255) / 256, 256>>>(Wo);
    k_gemm<<<NT_, 256, SMEM_BYTES>>>(bo);
    k_lse<<<32, 256>>>();
    k_fix<<<dim3((V_ / 8 + 255) / 256, B_), 256>>>(out);
}

// round 11
// speedup vs baseline: 1.2567x; 1.0776x over previous
#include <cuda_runtime.h>
#include <cuda_bf16.h>
#include <math_constants.h>
#include <stdint.h>

#define B_  2048
#define E_  128
#define V_  100000
#define NT_ 782   // ceil(V/128)
#define MT_ 16    // B/128
#define PAD_ 96.0f   // NT_*128 - V_

#define LOG2E_ 1.4426950408889634f
#define LN2_   0.6931471805599453f

#define LDSA 136                     // smem row stride in bf16 (128 + 8 pad)
#define TILE_BYTES (128 * LDSA * 2)  // 34816 per tile buffer
#define SM_A0 0
#define SM_A1 TILE_BYTES
#define SM_B  (2 * TILE_BYTES)
#define SM_BO (3 * TILE_BYTES)             // 512 B bias (permuted, pre-scaled)
#define SM_SUM (3 * TILE_BYTES + 512)      // 1024 B row partials
#define SMEM_BYTES (3 * TILE_BYTES + 512 + 1024)   // 105984

// column permutation: c=(j2,j1,j0,q1,q0,e) -> g=(j2,q1,q0,j1,j0,e)
// makes each lane's 4 bf16x2 epilogue values 8 consecutive global columns.
#define PERM6(c) (((c) & 0x21) | (((c) & 0x06) << 2) | (((c) & 0x18) >> 2))

// ---- scratch (no allocation allowed; device globals) ----
__device__ __nv_bfloat16 g_embb[B_ * E_];            // emb * log2e, bf16
__device__ __nv_bfloat16 g_woutb[(size_t)V_ * E_];   // W_out bf16 (25.6 MB)
__device__ __nv_bfloat16 g_logits[(size_t)B_ * V_];  // bf16 scaled logits (logit*log2e)
__device__ float g_psum[(size_t)NT_ * B_];           // [ntile][row] sumexp (coalesced)
__device__ float g_lse[B_];
__device__ int   g_is64;

// ================= helpers =================
__device__ __forceinline__ uint32_t smem_u32(const void* p) {
    uint32_t a;
    asm("{ .reg .u64 t; cvta.to.shared.u64 t, %1; cvt.u32.u64 %0, t; }" : "=r"(a) : "l"(p));
    return a;
}
__device__ __forceinline__ float ex2(float x) {
    float y;
    asm("ex2.approx.ftz.f32 %0, %1;" : "=f"(y) : "f"(x));
    return y;
}
__device__ __forceinline__ void cp16(uint32_t dst, const void* src) {
    asm volatile("cp.async.cg.shared.global [%0], [%1], 16;" :: "r"(dst), "l"(src));
}
__device__ __forceinline__ void cp16z(uint32_t dst, const void* src, int bytes) {
    asm volatile("cp.async.cg.shared.global [%0], [%1], 16, %2;"
                 :: "r"(dst), "l"(src), "r"(bytes));
}
#define CP_COMMIT() asm volatile("cp.async.commit_group;" ::: "memory")
#define CP_WAIT0()  asm volatile("cp.async.wait_group 0;" ::: "memory")

__device__ __forceinline__ void ldsm4(uint32_t* d, uint32_t a) {
    asm volatile("ldmatrix.sync.aligned.m8n8.x4.shared.b16 {%0,%1,%2,%3}, [%4];"
        : "=r"(d[0]), "=r"(d[1]), "=r"(d[2]), "=r"(d[3]) : "r"(a));
}
__device__ __forceinline__ void mma16816(float* c, const uint32_t* a, const uint32_t* b) {
    asm volatile("mma.sync.aligned.m16n8k16.row.col.f32.bf16.bf16.f32 "
        "{%0,%1,%2,%3}, {%4,%5,%6,%7}, {%8,%9}, {%0,%1,%2,%3};"
        : "+f"(c[0]), "+f"(c[1]), "+f"(c[2]), "+f"(c[3])
        : "r"(a[0]), "r"(a[1]), "r"(a[2]), "r"(a[3]), "r"(b[0]), "r"(b[1]));
}

// ---- dtype detection for center_word (jax int64 may actually be int32) ----
__global__ void k_detect(const void* __restrict__ cw) {
    __shared__ int ok;
    if (threadIdx.x == 0) ok = 1;
    __syncthreads();
    const int2* p = (const int2*)cw;
    int bad = 0;
    for (int i = threadIdx.x; i < 1024; i += 256) {
        int2 v = p[i];
        if (v.y != 0 || v.x < 0 || v.x >= V_) bad = 1;
    }
    if (bad) atomicAnd(&ok, 0);
    __syncthreads();
    if (threadIdx.x == 0) g_is64 = ok;
}

// emb scaled by log2e so the epilogue exp becomes a bare ex2
__global__ void k_gather(const void* __restrict__ cw,
                         const float* __restrict__ Wc,
                         const float* __restrict__ bc) {
    int b = blockIdx.x, e = threadIdx.x;
    long long idx;
    if (g_is64) idx = ((const long long*)cw)[b];
    else        idx = (long long)(((const int*)cw)[b]);
    float v = (Wc[(size_t)e * V_ + idx] + bc[e]) * LOG2E_;
    g_embb[b * E_ + e] = __float2bfloat16(v);
}

__global__ void k_cvt(const float* __restrict__ W) {
    size_t i = (size_t)blockIdx.x * blockDim.x + threadIdx.x;
    const size_t n4 = (size_t)V_ * E_ / 4;
    if (i >= n4) return;
    float4 f = ((const float4*)W)[i];
    __nv_bfloat162* o = (__nv_bfloat162*)g_woutb;
    o[2 * i + 0] = __floats2bfloat162_rn(f.x, f.y);
    o[2 * i + 1] = __floats2bfloat162_rn(f.z, f.w);
}

// ================= single GEMM pass =================
// One CTA per N-tile (128 cols of V), persistent over 16 M-tiles.
// 8 warps: 4(M) x 2(N); full warp tile 32M x 64N (acc[2][8][4]), 2 CTAs/SM.
// A double-buffered (prefetch before mainloop, wait after epilogue).
// B rows loaded PERMUTED (PERM6) so each lane's 4 epilogue bf16x2 values are
// 8 consecutive global columns -> direct STG.128 from registers, no staging.
// No bounds checks in sums (pad cols: zero B rows + zero bias -> ex2(0)=1;
// k_lse subtracts PAD_); STG keeps a 16B-chunk predicate.
__global__ void __launch_bounds__(256, 2)
k_gemm(const float* __restrict__ b_out) {
    extern __shared__ __align__(1024) char smem[];
    const uint32_t sb = smem_u32(smem);
    float* bo_s   = (float*)(smem + SM_BO);
    float* sm_sum = (float*)(smem + SM_SUM);

    const int ntile = blockIdx.x;
    const int n0 = ntile * 128;
    const int tid = threadIdx.x, lane = tid & 31, wid = tid >> 5;
    const int wm = wid >> 1, wn = wid & 1;

    // permuted bias (pre-scaled by log2e); pad cols -> 0
    if (tid < 128) {
        int gcol = n0 + (tid & 64) + PERM6(tid & 63);
        bo_s[tid] = (gcol < V_) ? b_out[gcol] * LOG2E_ : 0.f;
    }

    // ---- B tile (once, permuted rows) + A tile 0 ----
    #pragma unroll
    for (int li = tid; li < 2048; li += 256) {
        int r = li >> 4, c = li & 15;
        int v = n0 + (r & 64) + PERM6(r & 63);
        cp16z(sb + SM_B + (uint32_t)r * (LDSA * 2) + c * 16,
              g_woutb + (size_t)(v < V_ ? v : 0) * E_ + c * 8, (v < V_) ? 16 : 0);
    }
    #pragma unroll
    for (int li = tid; li < 2048; li += 256) {
        int r = li >> 4, c = li & 15;
        cp16(sb + SM_A0 + (uint32_t)r * (LDSA * 2) + c * 16,
             g_embb + (size_t)r * E_ + c * 8);
    }
    CP_COMMIT();
    CP_WAIT0();
    __syncthreads();

    const uint32_t a_lane = (uint32_t)(wm * 32 + (lane & 15)) * (LDSA * 2)
                          + ((lane >> 4) << 3) * 2;
    const uint32_t b_rowb = sb + SM_B
                          + (uint32_t)(wn * 64 + (lane & 7) + ((lane >> 4) << 3)) * (LDSA * 2)
                          + (((lane >> 3) & 1) << 3) * 2;
    const int qrow = lane >> 2, q = lane & 3;

    for (int it = 0; it < MT_; it++) {
        const int m0 = it * 128;
        const uint32_t a_base = sb + ((it & 1) ? SM_A1 : SM_A0) + a_lane;

        // prefetch next A tile into the other buffer (hidden under mainloop)
        if (it + 1 < MT_) {
            const uint32_t nb = sb + ((it & 1) ? SM_A0 : SM_A1);
            #pragma unroll
            for (int li = tid; li < 2048; li += 256) {
                int r = li >> 4, c = li & 15;
                cp16(nb + (uint32_t)r * (LDSA * 2) + c * 16,
                     g_embb + (size_t)(m0 + 128 + r) * E_ + c * 8);
            }
        }
        CP_COMMIT();

        // ---- mainloop: 128x128x128, full 32Mx64N warp tile ----
        float acc[2][8][4];
        #pragma unroll
        for (int i = 0; i < 2; i++)
            #pragma unroll
            for (int j = 0; j < 8; j++)
                #pragma unroll
                for (int k = 0; k < 4; k++) acc[i][j][k] = 0.f;

        #pragma unroll
        for (int ks = 0; ks < 8; ks++) {
            const uint32_t koff = (uint32_t)(ks * 16) * 2;
            uint32_t a0[4], a1[4], bb[4][4];
            ldsm4(a0, a_base + koff);
            ldsm4(a1, a_base + 16 * (LDSA * 2) + koff);
            #pragma unroll
            for (int nfp = 0; nfp < 4; nfp++)
                ldsm4(bb[nfp], b_rowb + (uint32_t)(nfp * 16) * (LDSA * 2) + koff);
            #pragma unroll
            for (int nfp = 0; nfp < 4; nfp++) {
                mma16816(acc[0][nfp * 2 + 0], a0, bb[nfp] + 0);
                mma16816(acc[0][nfp * 2 + 1], a0, bb[nfp] + 2);
                mma16816(acc[1][nfp * 2 + 0], a1, bb[nfp] + 0);
                mma16816(acc[1][nfp * 2 + 1], a1, bb[nfp] + 2);
            }
        }

        // ---- epilogue: ex2 sums + direct coalesced bf16 logit stores ----
        float rs[4];
        rs[0] = rs[1] = rs[2] = rs[3] = 0.f;
        #pragma unroll
        for (int mf = 0; mf < 2; mf++)
            #pragma unroll
            for (int h = 0; h < 2; h++) {
                const int rg = m0 + wm * 32 + mf * 16 + h * 8 + qrow;
                #pragma unroll
                for (int sub = 0; sub < 2; sub++) {
                    uint32_t pk[4];
                    float t0 = 0.f, t1 = 0.f;
                    #pragma unroll
                    for (int jn = 0; jn < 4; jn++) {
                        const int j = sub * 4 + jn;
                        const int c = wn * 64 + j * 8 + (q << 1);
                        float x0 = acc[mf][j][h * 2 + 0] + bo_s[c];
                        float x1 = acc[mf][j][h * 2 + 1] + bo_s[c + 1];
                        t0 += ex2(x0);
                        t1 += ex2(x1);
                        __nv_bfloat162 pv = __floats2bfloat162_rn(x0, x1);
                        pk[jn] = *(uint32_t*)&pv;
                    }
                    rs[mf * 2 + h] += t0 + t1;
                    const int gc = n0 + wn * 64 + sub * 32 + q * 8;
                    if (gc < V_)
                        __stcs((uint4*)(g_logits + (size_t)rg * V_ + gc),
                               make_uint4(pk[0], pk[1], pk[2], pk[3]));
                }
            }

        #pragma unroll
        for (int mf = 0; mf < 2; mf++)
            #pragma unroll
            for (int h = 0; h < 2; h++) {
                float t = rs[mf * 2 + h];
                t += __shfl_xor_sync(0xffffffffu, t, 1);
                t += __shfl_xor_sync(0xffffffffu, t, 2);
                if (q == 0) sm_sum[(wm * 32 + mf * 16 + h * 8 + qrow) * 2 + wn] = t;
            }
        __syncthreads();
        if (tid < 128)
            g_psum[(size_t)ntile * B_ + m0 + tid] =
                sm_sum[tid * 2] + sm_sum[tid * 2 + 1];

        if (it + 1 < MT_) {
            CP_WAIT0();      // next A tile (overlapped with mainloop+epilogue)
            __syncthreads();
        }
    }
}

// ---- combine partials -> per-row LSE; pad cols contribute exactly PAD_ ----
__global__ void k_lse() {   // grid 32, block 256
    __shared__ float sm[4][64];
    const int tid = threadIdx.x;
    const int r = (blockIdx.x << 6) + (tid & 63);
    const int jl = tid >> 6;
    float S = 0.f;
    for (int j = jl; j < NT_; j += 4)
        S += g_psum[(size_t)j * B_ + r];
    sm[jl][tid & 63] = S;
    __syncthreads();
    if (tid < 64) {
        float s = sm[0][tid] + sm[1][tid] + sm[2][tid] + sm[3][tid] - PAD_;
        g_lse[(blockIdx.x << 6) + tid] = __logf(s);
    }
}

// ---- streaming fixup: out = scaled_logit * ln2 - lse[row] ----
__global__ void __launch_bounds__(256) k_fix(float* __restrict__ out) {
    const int row = blockIdx.y;
    const int chunk = blockIdx.x * 256 + threadIdx.x;   // uint4 index in row
    if (chunk >= V_ / 8) return;
    const float l = g_lse[row];
    const uint4 v = __ldcs((const uint4*)(g_logits + (size_t)row * V_) + chunk);
    const __nv_bfloat162* bp = (const __nv_bfloat162*)&v;
    float4 o0, o1;
    float2 f;
    f = __bfloat1622float2(bp[0]); o0.x = fmaf(f.x, LN2_, -l); o0.y = fmaf(f.y, LN2_, -l);
    f = __bfloat1622float2(bp[1]); o0.z = fmaf(f.x, LN2_, -l); o0.w = fmaf(f.y, LN2_, -l);
    f = __bfloat1622float2(bp[2]); o1.x = fmaf(f.x, LN2_, -l); o1.y = fmaf(f.y, LN2_, -l);
    f = __bfloat1622float2(bp[3]); o1.z = fmaf(f.x, LN2_, -l); o1.w = fmaf(f.y, LN2_, -l);
    float4* dst = (float4*)(out + (size_t)row * V_ + (size_t)chunk * 8);
    __stcs(dst + 0, o0);
    __stcs(dst + 1, o1);
}

extern "C" void kernel_launch(void* const* d_in, const int* in_sizes, int n_in,
                              void* d_out, int out_size) {
    const void*  cw = d_in[0];
    const float* Wc = (const float*)d_in[1];
    const float* bc = (const float*)d_in[2];
    const float* Wo = (const float*)d_in[3];
    const float* bo = (const float*)d_in[4];
    float* out = (float*)d_out;

    cudaFuncSetAttribute(k_gemm, cudaFuncAttributeMaxDynamicSharedMemorySize, SMEM_BYTES);

    k_detect<<<1, 256>>>(cw);
    k_gather<<<B_, 128>>>(cw, Wc, bc);
    k_cvt<<<((V_ * E_ / 4) + 255) / 256, 256>>>(Wo);
    k_gemm<<<NT_, 256, SMEM_BYTES>>>(bo);
    k_lse<<<32, 256>>>();
    k_fix<<<dim3((V_ / 8 + 255) / 256, B_), 256>>>(out);
}

// round 12
// speedup vs baseline: 1.2569x; 1.0002x over previous
#include <cuda_runtime.h>
#include <cuda_bf16.h>
#include <math_constants.h>
#include <stdint.h>

#define B_  2048
#define E_  128
#define V_  100000
#define NT_ 782   // ceil(V/128)
#define MT_ 16    // B/128
#define PAD_ 96.0f   // NT_*128 - V_

#define LOG2E_ 1.4426950408889634f
#define LN2_   0.6931471805599453f

#define LDSA 136                     // smem row stride in bf16 (128 + 8 pad)
#define TILE_BYTES (128 * LDSA * 2)  // 34816 per tile buffer
#define SM_A0 0
#define SM_A1 TILE_BYTES
#define SM_B  (2 * TILE_BYTES)
#define SM_BO (3 * TILE_BYTES)             // 512 B bias (permuted, pre-scaled)
#define SM_SUM (3 * TILE_BYTES + 512)      // 1024 B row partials
#define SMEM_BYTES (3 * TILE_BYTES + 512 + 1024)   // 105984

// column permutation: c=(j2,j1,j0,q1,q0,e) -> g=(j2,q1,q0,j1,j0,e)
// makes each lane's 4 bf16x2 epilogue values 8 consecutive global columns.
#define PERM6(c) (((c) & 0x21) | (((c) & 0x06) << 2) | (((c) & 0x18) >> 2))

// ---- scratch (no allocation allowed; device globals) ----
__device__ __nv_bfloat16 g_embb[B_ * E_];            // emb * log2e, bf16
__device__ __nv_bfloat16 g_woutb[(size_t)V_ * E_];   // W_out bf16 (25.6 MB)
__device__ __nv_bfloat16 g_logits[(size_t)B_ * V_];  // bf16 scaled logits (logit*log2e)
__device__ float g_psum[(size_t)NT_ * B_];           // [ntile][row] sumexp (coalesced)
__device__ float g_lse[B_];
__device__ int   g_is64;

// ================= helpers =================
__device__ __forceinline__ uint32_t smem_u32(const void* p) {
    uint32_t a;
    asm("{ .reg .u64 t; cvta.to.shared.u64 t, %1; cvt.u32.u64 %0, t; }" : "=r"(a) : "l"(p));
    return a;
}
__device__ __forceinline__ float ex2(float x) {
    float y;
    asm("ex2.approx.ftz.f32 %0, %1;" : "=f"(y) : "f"(x));
    return y;
}
__device__ __forceinline__ void cp16(uint32_t dst, const void* src) {
    asm volatile("cp.async.cg.shared.global [%0], [%1], 16;" :: "r"(dst), "l"(src));
}
__device__ __forceinline__ void cp16z(uint32_t dst, const void* src, int bytes) {
    asm volatile("cp.async.cg.shared.global [%0], [%1], 16, %2;"
                 :: "r"(dst), "l"(src), "r"(bytes));
}
#define CP_COMMIT() asm volatile("cp.async.commit_group;" ::: "memory")
#define CP_WAIT0()  asm volatile("cp.async.wait_group 0;" ::: "memory")

__device__ __forceinline__ void ldsm4(uint32_t* d, uint32_t a) {
    asm volatile("ldmatrix.sync.aligned.m8n8.x4.shared.b16 {%0,%1,%2,%3}, [%4];"
        : "=r"(d[0]), "=r"(d[1]), "=r"(d[2]), "=r"(d[3]) : "r"(a));
}
__device__ __forceinline__ void mma16816(float* c, const uint32_t* a, const uint32_t* b) {
    asm volatile("mma.sync.aligned.m16n8k16.row.col.f32.bf16.bf16.f32 "
        "{%0,%1,%2,%3}, {%4,%5,%6,%7}, {%8,%9}, {%0,%1,%2,%3};"
        : "+f"(c[0]), "+f"(c[1]), "+f"(c[2]), "+f"(c[3])
        : "r"(a[0]), "r"(a[1]), "r"(a[2]), "r"(a[3]), "r"(b[0]), "r"(b[1]));
}

// ---- dtype detection for center_word (jax int64 may actually be int32) ----
__global__ void k_detect(const void* __restrict__ cw) {
    __shared__ int ok;
    if (threadIdx.x == 0) ok = 1;
    __syncthreads();
    const int2* p = (const int2*)cw;
    int bad = 0;
    for (int i = threadIdx.x; i < 1024; i += 256) {
        int2 v = p[i];
        if (v.y != 0 || v.x < 0 || v.x >= V_) bad = 1;
    }
    if (bad) atomicAnd(&ok, 0);
    __syncthreads();
    if (threadIdx.x == 0) g_is64 = ok;
}

// emb scaled by log2e so the epilogue exp becomes a bare ex2
__global__ void k_gather(const void* __restrict__ cw,
                         const float* __restrict__ Wc,
                         const float* __restrict__ bc) {
    int b = blockIdx.x, e = threadIdx.x;
    long long idx;
    if (g_is64) idx = ((const long long*)cw)[b];
    else        idx = (long long)(((const int*)cw)[b]);
    float v = (Wc[(size_t)e * V_ + idx] + bc[e]) * LOG2E_;
    g_embb[b * E_ + e] = __float2bfloat16(v);
}

__global__ void k_cvt(const float* __restrict__ W) {
    size_t i = (size_t)blockIdx.x * blockDim.x + threadIdx.x;
    const size_t n4 = (size_t)V_ * E_ / 4;
    if (i >= n4) return;
    float4 f = ((const float4*)W)[i];
    __nv_bfloat162* o = (__nv_bfloat162*)g_woutb;
    o[2 * i + 0] = __floats2bfloat162_rn(f.x, f.y);
    o[2 * i + 1] = __floats2bfloat162_rn(f.z, f.w);
}

// ================= single GEMM pass =================
// One CTA per N-tile (128 cols of V), persistent over 16 M-tiles.
// 8 warps: 4(M) x 2(N); full warp tile 32M x 64N (acc[2][8][4]), 2 CTAs/SM.
// A double-buffered (prefetch before mainloop, wait after epilogue).
// B rows loaded PERMUTED (PERM6) so each lane's 4 epilogue bf16x2 values are
// 8 consecutive global columns -> direct STG.128 from registers, no staging.
// No bounds checks in sums (pad cols: zero B rows + zero bias -> ex2(0)=1;
// k_lse subtracts PAD_); STG keeps a 16B-chunk predicate.
__global__ void __launch_bounds__(256, 2)
k_gemm(const float* __restrict__ b_out) {
    extern __shared__ __align__(1024) char smem[];
    const uint32_t sb = smem_u32(smem);
    float* bo_s   = (float*)(smem + SM_BO);
    float* sm_sum = (float*)(smem + SM_SUM);

    const int ntile = blockIdx.x;
    const int n0 = ntile * 128;
    const int tid = threadIdx.x, lane = tid & 31, wid = tid >> 5;
    const int wm = wid >> 1, wn = wid & 1;

    // permuted bias (pre-scaled by log2e); pad cols -> 0
    if (tid < 128) {
        int gcol = n0 + (tid & 64) + PERM6(tid & 63);
        bo_s[tid] = (gcol < V_) ? b_out[gcol] * LOG2E_ : 0.f;
    }

    // ---- B tile (once, permuted rows) + A tile 0 ----
    #pragma unroll
    for (int li = tid; li < 2048; li += 256) {
        int r = li >> 4, c = li & 15;
        int v = n0 + (r & 64) + PERM6(r & 63);
        cp16z(sb + SM_B + (uint32_t)r * (LDSA * 2) + c * 16,
              g_woutb + (size_t)(v < V_ ? v : 0) * E_ + c * 8, (v < V_) ? 16 : 0);
    }
    #pragma unroll
    for (int li = tid; li < 2048; li += 256) {
        int r = li >> 4, c = li & 15;
        cp16(sb + SM_A0 + (uint32_t)r * (LDSA * 2) + c * 16,
             g_embb + (size_t)r * E_ + c * 8);
    }
    CP_COMMIT();
    CP_WAIT0();
    __syncthreads();

    const uint32_t a_lane = (uint32_t)(wm * 32 + (lane & 15)) * (LDSA * 2)
                          + ((lane >> 4) << 3) * 2;
    const uint32_t b_rowb = sb + SM_B
                          + (uint32_t)(wn * 64 + (lane & 7) + ((lane >> 4) << 3)) * (LDSA * 2)
                          + (((lane >> 3) & 1) << 3) * 2;
    const int qrow = lane >> 2, q = lane & 3;

    for (int it = 0; it < MT_; it++) {
        const int m0 = it * 128;
        const uint32_t a_base = sb + ((it & 1) ? SM_A1 : SM_A0) + a_lane;

        // prefetch next A tile into the other buffer (hidden under mainloop)
        if (it + 1 < MT_) {
            const uint32_t nb = sb + ((it & 1) ? SM_A0 : SM_A1);
            #pragma unroll
            for (int li = tid; li < 2048; li += 256) {
                int r = li >> 4, c = li & 15;
                cp16(nb + (uint32_t)r * (LDSA * 2) + c * 16,
                     g_embb + (size_t)(m0 + 128 + r) * E_ + c * 8);
            }
        }
        CP_COMMIT();

        // ---- mainloop: 128x128x128, full 32Mx64N warp tile ----
        float acc[2][8][4];
        #pragma unroll
        for (int i = 0; i < 2; i++)
            #pragma unroll
            for (int j = 0; j < 8; j++)
                #pragma unroll
                for (int k = 0; k < 4; k++) acc[i][j][k] = 0.f;

        #pragma unroll
        for (int ks = 0; ks < 8; ks++) {
            const uint32_t koff = (uint32_t)(ks * 16) * 2;
            uint32_t a0[4], a1[4], bb[4][4];
            ldsm4(a0, a_base + koff);
            ldsm4(a1, a_base + 16 * (LDSA * 2) + koff);
            #pragma unroll
            for (int nfp = 0; nfp < 4; nfp++)
                ldsm4(bb[nfp], b_rowb + (uint32_t)(nfp * 16) * (LDSA * 2) + koff);
            #pragma unroll
            for (int nfp = 0; nfp < 4; nfp++) {
                mma16816(acc[0][nfp * 2 + 0], a0, bb[nfp] + 0);
                mma16816(acc[0][nfp * 2 + 1], a0, bb[nfp] + 2);
                mma16816(acc[1][nfp * 2 + 0], a1, bb[nfp] + 0);
                mma16816(acc[1][nfp * 2 + 1], a1, bb[nfp] + 2);
            }
        }

        // ---- epilogue: ex2 sums + direct coalesced bf16 logit stores ----
        float rs[4];
        rs[0] = rs[1] = rs[2] = rs[3] = 0.f;
        #pragma unroll
        for (int mf = 0; mf < 2; mf++)
            #pragma unroll
            for (int h = 0; h < 2; h++) {
                const int rg = m0 + wm * 32 + mf * 16 + h * 8 + qrow;
                #pragma unroll
                for (int sub = 0; sub < 2; sub++) {
                    uint32_t pk[4];
                    float t0 = 0.f, t1 = 0.f;
                    #pragma unroll
                    for (int jn = 0; jn < 4; jn++) {
                        const int j = sub * 4 + jn;
                        const int c = wn * 64 + j * 8 + (q << 1);
                        float x0 = acc[mf][j][h * 2 + 0] + bo_s[c];
                        float x1 = acc[mf][j][h * 2 + 1] + bo_s[c + 1];
                        t0 += ex2(x0);
                        t1 += ex2(x1);
                        __nv_bfloat162 pv = __floats2bfloat162_rn(x0, x1);
                        pk[jn] = *(uint32_t*)&pv;
                    }
                    rs[mf * 2 + h] += t0 + t1;
                    const int gc = n0 + wn * 64 + sub * 32 + q * 8;
                    if (gc < V_)
                        __stcs((uint4*)(g_logits + (size_t)rg * V_ + gc),
                               make_uint4(pk[0], pk[1], pk[2], pk[3]));
                }
            }

        #pragma unroll
        for (int mf = 0; mf < 2; mf++)
            #pragma unroll
            for (int h = 0; h < 2; h++) {
                float t = rs[mf * 2 + h];
                t += __shfl_xor_sync(0xffffffffu, t, 1);
                t += __shfl_xor_sync(0xffffffffu, t, 2);
                if (q == 0) sm_sum[(wm * 32 + mf * 16 + h * 8 + qrow) * 2 + wn] = t;
            }
        __syncthreads();
        if (tid < 128)
            g_psum[(size_t)ntile * B_ + m0 + tid] =
                sm_sum[tid * 2] + sm_sum[tid * 2 + 1];

        if (it + 1 < MT_) {
            CP_WAIT0();      // next A tile (overlapped with mainloop+epilogue)
            __syncthreads();
        }
    }
}

// ---- combine partials -> per-row LSE; pad cols contribute exactly PAD_ ----
__global__ void k_lse() {   // grid 32, block 256
    __shared__ float sm[4][64];
    const int tid = threadIdx.x;
    const int r = (blockIdx.x << 6) + (tid & 63);
    const int jl = tid >> 6;
    float S = 0.f;
    for (int j = jl; j < NT_; j += 4)
        S += g_psum[(size_t)j * B_ + r];
    sm[jl][tid & 63] = S;
    __syncthreads();
    if (tid < 64) {
        float s = sm[0][tid] + sm[1][tid] + sm[2][tid] + sm[3][tid] - PAD_;
        g_lse[(blockIdx.x << 6) + tid] = __logf(s);
    }
}

// ---- streaming fixup: out = scaled_logit * ln2 - lse[row] ----
__global__ void __launch_bounds__(256) k_fix(float* __restrict__ out) {
    const int row = blockIdx.y;
    const int chunk = blockIdx.x * 256 + threadIdx.x;   // uint4 index in row
    if (chunk >= V_ / 8) return;
    const float l = g_lse[row];
    const uint4 v = __ldcs((const uint4*)(g_logits + (size_t)row * V_) + chunk);
    const __nv_bfloat162* bp = (const __nv_bfloat162*)&v;
    float4 o0, o1;
    float2 f;
    f = __bfloat1622float2(bp[0]); o0.x = fmaf(f.x, LN2_, -l); o0.y = fmaf(f.y, LN2_, -l);
    f = __bfloat1622float2(bp[1]); o0.z = fmaf(f.x, LN2_, -l); o0.w = fmaf(f.y, LN2_, -l);
    f = __bfloat1622float2(bp[2]); o1.x = fmaf(f.x, LN2_, -l); o1.y = fmaf(f.y, LN2_, -l);
    f = __bfloat1622float2(bp[3]); o1.z = fmaf(f.x, LN2_, -l); o1.w = fmaf(f.y, LN2_, -l);
    float4* dst = (float4*)(out + (size_t)row * V_ + (size_t)chunk * 8);
    __stcs(dst + 0, o0);
    __stcs(dst + 1, o1);
}

extern "C" void kernel_launch(void* const* d_in, const int* in_sizes, int n_in,
                              void* d_out, int out_size) {
    const void*  cw = d_in[0];
    const float* Wc = (const float*)d_in[1];
    const float* bc = (const float*)d_in[2];
    const float* Wo = (const float*)d_in[3];
    const float* bo = (const float*)d_in[4];
    float* out = (float*)d_out;

    cudaFuncSetAttribute(k_gemm, cudaFuncAttributeMaxDynamicSharedMemorySize, SMEM_BYTES);

    k_detect<<<1, 256>>>(cw);
    k_gather<<<B_, 128>>>(cw, Wc, bc);
    k_cvt<<<((V_ * E_ / 4) + 255) / 256, 256>>>(Wo);
    k_gemm<<<NT_, 256, SMEM_BYTES>>>(bo);
    k_lse<<<32, 256>>>();
    k_fix<<<dim3((V_ / 8 + 255) / 256, B_), 256>>>(out);
}